// round 8
// baseline (speedup 1.0000x reference)
#include <cuda_runtime.h>
#include <cuda_fp16.h>
#include <math.h>

#define B_   1024
#define L_   32
#define K_   8
#define G_   8
#define C_   128
#define S_   32
#define GRID_MAIN 148
#define NTILES 32              // tiles of 256 rows (32 batch elems)
#define NITEMS (L_ * NTILES)   // 1024

__device__ unsigned char g_ci[B_ * L_];
__device__ unsigned int g_mask[B_ * G_ * L_];

// ---------- helpers ----------
__device__ __forceinline__ unsigned pack2h(float lo, float hi) {
    unsigned r;
    asm("cvt.rn.f16x2.f32 %0, %1, %2;" : "=r"(r) : "f"(hi), "f"(lo));
    return r;
}
__device__ __forceinline__ float silu_f(float x) {
    float h = 0.5f * x, t;
    asm("tanh.approx.f32 %0, %1;" : "=f"(t) : "f"(h));
    return fmaf(h, t, h);
}
__device__ __forceinline__ void mma_f16(float* c,
    unsigned a0, unsigned a1, unsigned a2, unsigned a3, unsigned b0, unsigned b1) {
    asm("mma.sync.aligned.m16n8k16.row.col.f32.f16.f16.f32 "
        "{%0,%1,%2,%3},{%4,%5,%6,%7},{%8,%9},{%0,%1,%2,%3};"
        : "+f"(c[0]), "+f"(c[1]), "+f"(c[2]), "+f"(c[3])
        : "r"(a0), "r"(a1), "r"(a2), "r"(a3), "r"(b0), "r"(b1));
}
__device__ __forceinline__ float xval(int d, unsigned Mw, bool tfl, int tgt,
                                      const float* zr, const float* zh) {
    if (d < 32)  return ((Mw >> d) & 1u) ? zr[d] : 0.0f;
    if (d < 64)  return (float)((Mw >> (d - 32)) & 1u);
    if (d < 72)  return (tfl && (d - 64) == tgt) ? 1.0f : 0.0f;
    if (d < 104) return zh[d - 72];
    return 0.0f;
}

// ---------- merged prep ----------
__global__ void prep_kernel(const float* __restrict__ tp, const float* __restrict__ ug,
                            const float* __restrict__ th, const float* __restrict__ ga,
                            const float* __restrict__ u_adj, float* __restrict__ out) {
    __shared__ unsigned char sc[L_];
    __shared__ float sep[K_ * K_];
    int b = blockIdx.x, t = threadIdx.x;
    if (t < L_) {
        const float* u = ug + (b * L_ + t) * K_;
        float best = -1e30f; int bi = 0;
#pragma unroll
        for (int k = 0; k < K_; k++) {
            float gum = -logf(-logf(u[k] + 1e-10f) + 1e-10f);
            float v = tp[t * K_ + k] + gum;
            if (v > best) { best = v; bi = k; }
        }
        sc[t] = (unsigned char)bi;
        g_ci[b * L_ + t] = (unsigned char)bi;
    } else if (t >= 64 && t < 128) {
        int e = t - 64;
        float s1 = 1.0f / (1.0f + expf(-th[e]));
        float s2 = 1.0f / (1.0f + expf(-ga[e]));
        sep[e] = s1 * s2;
    }
    if (t == 0) out[b] = 0.0f;
    __syncthreads();
    int g = t >> 5, l = t & 31;
    int cl = sc[l];
    unsigned bits = 0;
#pragma unroll
    for (int cj = 0; cj < K_; cj++) {
        float u = u_adj[((b * G_ + g) * K_ + cj) * K_ + cl];
        bits |= (u < sep[cj * K_ + cl]) ? (1u << cj) : 0u;
    }
    unsigned wv = 0;
#pragma unroll
    for (int j = 0; j < L_; j++) {
        unsigned mj = (bits >> sc[j]) & 1u;
        if (j == l) mj = 0;
        wv |= mj << j;
    }
    g_mask[(b * G_ + g) * L_ + l] = wv;
}

// ---------- smem layout (bytes) ----------
#define OFF_W1   0
#define OFF_W2   40960
#define OFF_SZS  81920
#define OFF_SZSH 86016
#define OFF_B1   90112
#define OFF_G1W  90624
#define OFF_G1B  91136
#define OFF_B2   91648
#define OFF_G2W  92160
#define OFF_G2B  92672
#define OFF_W3   93184
#define SMEM_BYTES 95232

__global__ __launch_bounds__(256, 1) void main_kernel(
    const float* __restrict__ z_sample, const int* __restrict__ target,
    const float* __restrict__ z_mean,   const float* __restrict__ z_logstd,
    const float* __restrict__ z_shared,
    const float* __restrict__ W1, const float* __restrict__ b1g,
    const float* __restrict__ g1wg, const float* __restrict__ g1bg,
    const float* __restrict__ W2, const float* __restrict__ b2g,
    const float* __restrict__ g2wg, const float* __restrict__ g2bg,
    const float* __restrict__ W3g, const float* __restrict__ b3g,
    const float* __restrict__ tsc, float* __restrict__ out)
{
    extern __shared__ char smem[];
    uint2*  W1u2 = (uint2*)(smem + OFF_W1);
    uint2*  W2u2 = (uint2*)(smem + OFF_W2);
    const uint4* W1q4 = (const uint4*)(smem + OFF_W1);
    const uint4* W2q4 = (const uint4*)(smem + OFF_W2);
    float*  szs  = (float*)(smem + OFF_SZS);
    float*  szsh = (float*)(smem + OFF_SZSH);
    float2* sB1  = (float2*)(smem + OFF_B1);
    float2* sG1w = (float2*)(smem + OFF_G1W);
    float2* sG1b = (float2*)(smem + OFF_G1B);
    float2* sB2  = (float2*)(smem + OFF_B2);
    float2* sG2w = (float2*)(smem + OFF_G2W);
    float2* sG2b = (float2*)(smem + OFF_G2B);
    float4* sW3  = (float4*)(smem + OFF_W3);

    const int tid = threadIdx.x;
    const int wid = tid >> 5;
    const int lane = tid & 31;
    const int gid = lane >> 2;
    const int t4 = lane & 3;

    const int start = (int)(((long long)blockIdx.x * NITEMS) / GRID_MAIN);
    const int end   = (int)(((long long)(blockIdx.x + 1) * NITEMS) / GRID_MAIN);

    int cur_l = -1;
    float b3_0 = 0.f, b3_1 = 0.f, sc0 = 1.f, sc1 = 1.f, isc0 = 1.f, isc1 = 1.f;

    for (int item = start; item < end; item++) {
        const int l = item >> 5;
        const int tile = item & 31;

        if (l != cur_l) {
            __syncthreads();
            const float* W1g = W1 + l * C_ * 104;
            for (int idx = tid; idx < 128 * 32; idx += 256) {
                int c = idx >> 5, s = idx & 31;
                int kk = s >> 2, tq = s & 3;
                int d0 = kk * 16 + tq * 2, d1 = d0 + 8;
                float w00 = (d0     < 104) ? W1g[c * 104 + d0]     : 0.0f;
                float w01 = (d0 + 1 < 104) ? W1g[c * 104 + d0 + 1] : 0.0f;
                float w10 = (d1     < 104) ? W1g[c * 104 + d1]     : 0.0f;
                float w11 = (d1 + 1 < 104) ? W1g[c * 104 + d1 + 1] : 0.0f;
                W1u2[c * 40 + (kk >> 1) * 8 + tq * 2 + (kk & 1)] =
                    make_uint2(pack2h(w00, w01), pack2h(w10, w11));
            }
            const float* W2g = W2 + l * C_ * C_;
            for (int idx = tid; idx < 128 * 32; idx += 256) {
                int c = idx >> 5, s = idx & 31;
                int kk = s >> 2, tq = s & 3;
                int d0 = kk * 16 + tq * 2, d1 = d0 + 8;
                W2u2[c * 40 + (kk >> 1) * 8 + tq * 2 + (kk & 1)] =
                    make_uint2(pack2h(W2g[c * C_ + d0], W2g[c * C_ + d0 + 1]),
                               pack2h(W2g[c * C_ + d1], W2g[c * C_ + d1 + 1]));
            }
            if (tid < 64) {
                sB1[tid]  = ((const float2*)(b1g  + l * C_))[tid];
                sG1w[tid] = ((const float2*)(g1wg + l * C_))[tid];
                sG1b[tid] = ((const float2*)(g1bg + l * C_))[tid];
                sB2[tid]  = ((const float2*)(b2g  + l * C_))[tid];
                sG2w[tid] = ((const float2*)(g2wg + l * C_))[tid];
                sG2b[tid] = ((const float2*)(g2bg + l * C_))[tid];
                int c0 = 2 * tid;
                sW3[tid] = make_float4(W3g[l * 2 * C_ + c0], W3g[l * 2 * C_ + C_ + c0],
                                       W3g[l * 2 * C_ + c0 + 1], W3g[l * 2 * C_ + C_ + c0 + 1]);
            }
            b3_0 = b3g[l * 2]; b3_1 = b3g[l * 2 + 1];
            sc0 = __expf(tsc[l * 2]); sc1 = __expf(tsc[l * 2 + 1]);
            isc0 = 1.0f / sc0; isc1 = 1.0f / sc1;
            __syncthreads();
            cur_l = l;
        }

        // stage z rows for this tile (32 b's)
        __syncthreads();
        for (int idx = tid; idx < 1024; idx += 256) {
            szs[idx]  = z_sample[tile * 32 * L_ + idx];
            szsh[idx] = z_shared[tile * 32 * S_ + idx];
        }
        __syncthreads();

        // warp owns 32 rows: 4 groups of 8; thread rows = gid + {0,8,16,24}
        int bq_[4];
        unsigned Mw[4];
        bool tf[4];
        int tg[4];
        const float* zr[4];
        const float* zh[4];
#pragma unroll
        for (int k = 0; k < 4; k++) {
            int grow = tile * 256 + wid * 32 + k * 8 + gid;
            int bb = tile * 32 + wid * 4 + k;
            bq_[k] = bb;
            Mw[k] = g_mask[grow * L_ + l];
            tg[k] = target[bb];
            tf[k] = (g_ci[bb * L_ + l] == tg[k]);
            zr[k] = szs + (wid * 4 + k) * 32;
            zh[k] = szsh + (wid * 4 + k) * 32;
        }

        // ---- build A1 fragments ----
        unsigned Ah0[7][4], Ah1[7][4];
#pragma unroll
        for (int kk = 0; kk < 7; kk++) {
            int db = kk * 16 + t4 * 2;
            Ah0[kk][0] = pack2h(xval(db,     Mw[0], tf[0], tg[0], zr[0], zh[0]),
                                xval(db + 1, Mw[0], tf[0], tg[0], zr[0], zh[0]));
            Ah0[kk][1] = pack2h(xval(db,     Mw[1], tf[1], tg[1], zr[1], zh[1]),
                                xval(db + 1, Mw[1], tf[1], tg[1], zr[1], zh[1]));
            Ah0[kk][2] = pack2h(xval(db + 8, Mw[0], tf[0], tg[0], zr[0], zh[0]),
                                xval(db + 9, Mw[0], tf[0], tg[0], zr[0], zh[0]));
            Ah0[kk][3] = pack2h(xval(db + 8, Mw[1], tf[1], tg[1], zr[1], zh[1]),
                                xval(db + 9, Mw[1], tf[1], tg[1], zr[1], zh[1]));
            Ah1[kk][0] = pack2h(xval(db,     Mw[2], tf[2], tg[2], zr[2], zh[2]),
                                xval(db + 1, Mw[2], tf[2], tg[2], zr[2], zh[2]));
            Ah1[kk][1] = pack2h(xval(db,     Mw[3], tf[3], tg[3], zr[3], zh[3]),
                                xval(db + 1, Mw[3], tf[3], tg[3], zr[3], zh[3]));
            Ah1[kk][2] = pack2h(xval(db + 8, Mw[2], tf[2], tg[2], zr[2], zh[2]),
                                xval(db + 9, Mw[2], tf[2], tg[2], zr[2], zh[2]));
            Ah1[kk][3] = pack2h(xval(db + 8, Mw[3], tf[3], tg[3], zr[3], zh[3]),
                                xval(db + 9, Mw[3], tf[3], tg[3], zr[3], zh[3]));
        }

        // ---- MMA1 (both row groups share every B fragment) ----
        float acc0[16][4], acc1[16][4];
#pragma unroll
        for (int nt = 0; nt < 16; nt++)
#pragma unroll
            for (int i = 0; i < 4; i++) { acc0[nt][i] = 0.0f; acc1[nt][i] = 0.0f; }

#pragma unroll
        for (int nt = 0; nt < 16; nt++) {
            const uint4* bp = W1q4 + (nt * 8 + gid) * 20 + t4;
#pragma unroll
            for (int j = 0; j < 4; j++) {
                uint4 bqv = bp[j * 4];
                mma_f16(acc0[nt], Ah0[2*j][0], Ah0[2*j][1], Ah0[2*j][2], Ah0[2*j][3], bqv.x, bqv.y);
                mma_f16(acc1[nt], Ah1[2*j][0], Ah1[2*j][1], Ah1[2*j][2], Ah1[2*j][3], bqv.x, bqv.y);
                if (j < 3) {
                    mma_f16(acc0[nt], Ah0[2*j+1][0], Ah0[2*j+1][1], Ah0[2*j+1][2], Ah0[2*j+1][3], bqv.z, bqv.w);
                    mma_f16(acc1[nt], Ah1[2*j+1][0], Ah1[2*j+1][1], Ah1[2*j+1][2], Ah1[2*j+1][3], bqv.z, bqv.w);
                }
            }
        }

        // ---- GN1 + SiLU -> A2 fragments ----
        float s[4] = {0.f, 0.f, 0.f, 0.f}, q[4] = {0.f, 0.f, 0.f, 0.f};
#pragma unroll
        for (int nt = 0; nt < 16; nt++) {
            float2 bb = sB1[nt * 4 + t4];
            acc0[nt][0] += bb.x; acc0[nt][1] += bb.y;
            acc0[nt][2] += bb.x; acc0[nt][3] += bb.y;
            acc1[nt][0] += bb.x; acc1[nt][1] += bb.y;
            acc1[nt][2] += bb.x; acc1[nt][3] += bb.y;
            s[0] += acc0[nt][0] + acc0[nt][1]; q[0] += acc0[nt][0]*acc0[nt][0] + acc0[nt][1]*acc0[nt][1];
            s[1] += acc0[nt][2] + acc0[nt][3]; q[1] += acc0[nt][2]*acc0[nt][2] + acc0[nt][3]*acc0[nt][3];
            s[2] += acc1[nt][0] + acc1[nt][1]; q[2] += acc1[nt][0]*acc1[nt][0] + acc1[nt][1]*acc1[nt][1];
            s[3] += acc1[nt][2] + acc1[nt][3]; q[3] += acc1[nt][2]*acc1[nt][2] + acc1[nt][3]*acc1[nt][3];
        }
#pragma unroll
        for (int o = 1; o <= 2; o <<= 1)
#pragma unroll
            for (int k = 0; k < 4; k++) {
                s[k] += __shfl_xor_sync(0xffffffffu, s[k], o);
                q[k] += __shfl_xor_sync(0xffffffffu, q[k], o);
            }
        float mu[4], inv[4];
#pragma unroll
        for (int k = 0; k < 4; k++) {
            mu[k] = s[k] * (1.0f / 128.0f);
            inv[k] = rsqrtf(q[k] * (1.0f / 128.0f) - mu[k] * mu[k] + 1e-5f);
        }

        unsigned A2h0[8][4], A2h1[8][4];
#pragma unroll
        for (int kk = 0; kk < 8; kk++) {
            int nt0 = 2 * kk, nt1 = 2 * kk + 1;
            float2 w0 = sG1w[nt0 * 4 + t4], c0v = sG1b[nt0 * 4 + t4];
            float2 w1 = sG1w[nt1 * 4 + t4], c1v = sG1b[nt1 * 4 + t4];
            A2h0[kk][0] = pack2h(silu_f((acc0[nt0][0] - mu[0]) * inv[0] * w0.x + c0v.x),
                                 silu_f((acc0[nt0][1] - mu[0]) * inv[0] * w0.y + c0v.y));
            A2h0[kk][1] = pack2h(silu_f((acc0[nt0][2] - mu[1]) * inv[1] * w0.x + c0v.x),
                                 silu_f((acc0[nt0][3] - mu[1]) * inv[1] * w0.y + c0v.y));
            A2h0[kk][2] = pack2h(silu_f((acc0[nt1][0] - mu[0]) * inv[0] * w1.x + c1v.x),
                                 silu_f((acc0[nt1][1] - mu[0]) * inv[0] * w1.y + c1v.y));
            A2h0[kk][3] = pack2h(silu_f((acc0[nt1][2] - mu[1]) * inv[1] * w1.x + c1v.x),
                                 silu_f((acc0[nt1][3] - mu[1]) * inv[1] * w1.y + c1v.y));
            A2h1[kk][0] = pack2h(silu_f((acc1[nt0][0] - mu[2]) * inv[2] * w0.x + c0v.x),
                                 silu_f((acc1[nt0][1] - mu[2]) * inv[2] * w0.y + c0v.y));
            A2h1[kk][1] = pack2h(silu_f((acc1[nt0][2] - mu[3]) * inv[3] * w0.x + c0v.x),
                                 silu_f((acc1[nt0][3] - mu[3]) * inv[3] * w0.y + c0v.y));
            A2h1[kk][2] = pack2h(silu_f((acc1[nt1][0] - mu[2]) * inv[2] * w1.x + c1v.x),
                                 silu_f((acc1[nt1][1] - mu[2]) * inv[2] * w1.y + c1v.y));
            A2h1[kk][3] = pack2h(silu_f((acc1[nt1][2] - mu[3]) * inv[3] * w1.x + c1v.x),
                                 silu_f((acc1[nt1][3] - mu[3]) * inv[3] * w1.y + c1v.y));
        }

        // ---- MMA2 ----
#pragma unroll
        for (int nt = 0; nt < 16; nt++)
#pragma unroll
            for (int i = 0; i < 4; i++) { acc0[nt][i] = 0.0f; acc1[nt][i] = 0.0f; }

#pragma unroll
        for (int nt = 0; nt < 16; nt++) {
            const uint4* bp = W2q4 + (nt * 8 + gid) * 20 + t4;
#pragma unroll
            for (int j = 0; j < 4; j++) {
                uint4 bqv = bp[j * 4];
                mma_f16(acc0[nt], A2h0[2*j][0], A2h0[2*j][1], A2h0[2*j][2], A2h0[2*j][3], bqv.x, bqv.y);
                mma_f16(acc1[nt], A2h1[2*j][0], A2h1[2*j][1], A2h1[2*j][2], A2h1[2*j][3], bqv.x, bqv.y);
                mma_f16(acc0[nt], A2h0[2*j+1][0], A2h0[2*j+1][1], A2h0[2*j+1][2], A2h0[2*j+1][3], bqv.z, bqv.w);
                mma_f16(acc1[nt], A2h1[2*j+1][0], A2h1[2*j+1][1], A2h1[2*j+1][2], A2h1[2*j+1][3], bqv.z, bqv.w);
            }
        }

        // ---- GN2 + SiLU + layer3 + KL ----
#pragma unroll
        for (int k = 0; k < 4; k++) { s[k] = 0.f; q[k] = 0.f; }
#pragma unroll
        for (int nt = 0; nt < 16; nt++) {
            float2 bb = sB2[nt * 4 + t4];
            acc0[nt][0] += bb.x; acc0[nt][1] += bb.y;
            acc0[nt][2] += bb.x; acc0[nt][3] += bb.y;
            acc1[nt][0] += bb.x; acc1[nt][1] += bb.y;
            acc1[nt][2] += bb.x; acc1[nt][3] += bb.y;
            s[0] += acc0[nt][0] + acc0[nt][1]; q[0] += acc0[nt][0]*acc0[nt][0] + acc0[nt][1]*acc0[nt][1];
            s[1] += acc0[nt][2] + acc0[nt][3]; q[1] += acc0[nt][2]*acc0[nt][2] + acc0[nt][3]*acc0[nt][3];
            s[2] += acc1[nt][0] + acc1[nt][1]; q[2] += acc1[nt][0]*acc1[nt][0] + acc1[nt][1]*acc1[nt][1];
            s[3] += acc1[nt][2] + acc1[nt][3]; q[3] += acc1[nt][2]*acc1[nt][2] + acc1[nt][3]*acc1[nt][3];
        }
#pragma unroll
        for (int o = 1; o <= 2; o <<= 1)
#pragma unroll
            for (int k = 0; k < 4; k++) {
                s[k] += __shfl_xor_sync(0xffffffffu, s[k], o);
                q[k] += __shfl_xor_sync(0xffffffffu, q[k], o);
            }
#pragma unroll
        for (int k = 0; k < 4; k++) {
            mu[k] = s[k] * (1.0f / 128.0f);
            inv[k] = rsqrtf(q[k] * (1.0f / 128.0f) - mu[k] * mu[k] + 1e-5f);
        }

        float p0[4] = {0.f, 0.f, 0.f, 0.f}, p1[4] = {0.f, 0.f, 0.f, 0.f};
#pragma unroll
        for (int nt = 0; nt < 16; nt++) {
            float2 wv = sG2w[nt * 4 + t4], bv = sG2b[nt * 4 + t4];
            float4 w3 = sW3[nt * 4 + t4];
            float h0 = silu_f((acc0[nt][0] - mu[0]) * inv[0] * wv.x + bv.x);
            float h1 = silu_f((acc0[nt][1] - mu[0]) * inv[0] * wv.y + bv.y);
            float h2 = silu_f((acc0[nt][2] - mu[1]) * inv[1] * wv.x + bv.x);
            float h3 = silu_f((acc0[nt][3] - mu[1]) * inv[1] * wv.y + bv.y);
            float h4 = silu_f((acc1[nt][0] - mu[2]) * inv[2] * wv.x + bv.x);
            float h5 = silu_f((acc1[nt][1] - mu[2]) * inv[2] * wv.y + bv.y);
            float h6 = silu_f((acc1[nt][2] - mu[3]) * inv[3] * wv.x + bv.x);
            float h7 = silu_f((acc1[nt][3] - mu[3]) * inv[3] * wv.y + bv.y);
            p0[0] += h0 * w3.x + h1 * w3.z;  p1[0] += h0 * w3.y + h1 * w3.w;
            p0[1] += h2 * w3.x + h3 * w3.z;  p1[1] += h2 * w3.y + h3 * w3.w;
            p0[2] += h4 * w3.x + h5 * w3.z;  p1[2] += h4 * w3.y + h5 * w3.w;
            p0[3] += h6 * w3.x + h7 * w3.z;  p1[3] += h6 * w3.y + h7 * w3.w;
        }
#pragma unroll
        for (int o = 1; o <= 2; o <<= 1)
#pragma unroll
            for (int k = 0; k < 4; k++) {
                p0[k] += __shfl_xor_sync(0xffffffffu, p0[k], o);
                p1[k] += __shfl_xor_sync(0xffffffffu, p1[k], o);
            }
        if (t4 == 0) {
#pragma unroll
            for (int k = 0; k < 4; k++) {
                int bb = bq_[k];
                float o0 = p0[k] + b3_0, o1 = p1[k] + b3_1;
                float pm = tanhf(o0 * isc0) * sc0;
                float pl = tanhf(o1 * isc1) * sc1;
                float zl = z_logstd[bb * L_ + l], zmn = z_mean[bb * L_ + l];
                float dmu = zmn - pm;
                float kld = pl - zl + (__expf(2.0f * zl) + dmu * dmu) * 0.5f * __expf(-2.0f * pl) - 0.5f;
                atomicAdd(out + bb, kld * 0.125f);
            }
        }
    }
}

extern "C" void kernel_launch(void* const* d_in, const int* in_sizes, int n_in,
                              void* d_out, int out_size) {
    const float* z_sample      = (const float*)d_in[0];
    const int*   target        = (const int*)  d_in[1];
    const float* z_mean        = (const float*)d_in[2];
    const float* z_logstd      = (const float*)d_in[3];
    const float* z_shared      = (const float*)d_in[4];
    const float* u_gumbel      = (const float*)d_in[5];
    const float* u_adj         = (const float*)d_in[6];
    const float* target_params = (const float*)d_in[7];
    const float* enco_theta    = (const float*)d_in[8];
    const float* enco_gamma    = (const float*)d_in[9];
    const float* W1            = (const float*)d_in[10];
    const float* b1            = (const float*)d_in[11];
    const float* gn1_w         = (const float*)d_in[12];
    const float* gn1_b         = (const float*)d_in[13];
    const float* W2            = (const float*)d_in[14];
    const float* b2            = (const float*)d_in[15];
    const float* gn2_w         = (const float*)d_in[16];
    const float* gn2_b         = (const float*)d_in[17];
    const float* W3            = (const float*)d_in[18];
    const float* b3            = (const float*)d_in[19];
    const float* tanh_scale    = (const float*)d_in[20];
    float* out = (float*)d_out;

    prep_kernel<<<B_, 256>>>(target_params, u_gumbel, enco_theta, enco_gamma, u_adj, out);

    cudaFuncSetAttribute(main_kernel, cudaFuncAttributeMaxDynamicSharedMemorySize, SMEM_BYTES);
    main_kernel<<<GRID_MAIN, 256, SMEM_BYTES>>>(
        z_sample, target, z_mean, z_logstd, z_shared,
        W1, b1, gn1_w, gn1_b, W2, b2, gn2_w, gn2_b, W3, b3, tanh_scale, out);
}

// round 9
// speedup vs baseline: 1.0152x; 1.0152x over previous
#include <cuda_runtime.h>
#include <cuda_fp16.h>
#include <math.h>

#define B_   1024
#define L_   32
#define K_   8
#define G_   8
#define C_   128
#define S_   32
#define GRID_MAIN 148
#define NTILES 32              // tiles of 256 rows (32 batch elems)
#define NITEMS (L_ * NTILES)   // 1024

__device__ unsigned char g_ci[B_ * L_];
__device__ unsigned int g_mask[B_ * G_ * L_];

// ---------- helpers ----------
__device__ __forceinline__ unsigned pack2h(float lo, float hi) {
    unsigned r;
    asm("cvt.rn.f16x2.f32 %0, %1, %2;" : "=r"(r) : "f"(hi), "f"(lo));
    return r;
}
__device__ __forceinline__ float2 unpack2h(unsigned u) {
    __half2 h = *reinterpret_cast<__half2*>(&u);
    return __half22float2(h);
}
__device__ __forceinline__ float silu_f(float x) {
    float h = 0.5f * x, t;
    asm("tanh.approx.f32 %0, %1;" : "=f"(t) : "f"(h));
    return fmaf(h, t, h);
}
__device__ __forceinline__ void mma_f16(float* c,
    unsigned a0, unsigned a1, unsigned a2, unsigned a3, unsigned b0, unsigned b1) {
    asm("mma.sync.aligned.m16n8k16.row.col.f32.f16.f16.f32 "
        "{%0,%1,%2,%3},{%4,%5,%6,%7},{%8,%9},{%0,%1,%2,%3};"
        : "+f"(c[0]), "+f"(c[1]), "+f"(c[2]), "+f"(c[3])
        : "r"(a0), "r"(a1), "r"(a2), "r"(a3), "r"(b0), "r"(b1));
}
__device__ __forceinline__ float xval(int d, unsigned Mw, bool tfl, int tgt,
                                      const float* zr, const float* zh) {
    if (d < 32)  return ((Mw >> d) & 1u) ? zr[d] : 0.0f;
    if (d < 64)  return (float)((Mw >> (d - 32)) & 1u);
    if (d < 72)  return (tfl && (d - 64) == tgt) ? 1.0f : 0.0f;
    if (d < 104) return zh[d - 72];
    return 0.0f;
}

// ---------- merged prep ----------
__global__ void prep_kernel(const float* __restrict__ tp, const float* __restrict__ ug,
                            const float* __restrict__ th, const float* __restrict__ ga,
                            const float* __restrict__ u_adj, float* __restrict__ out) {
    __shared__ unsigned char sc[L_];
    __shared__ float sep[K_ * K_];
    int b = blockIdx.x, t = threadIdx.x;
    if (t < L_) {
        const float* u = ug + (b * L_ + t) * K_;
        float best = -1e30f; int bi = 0;
#pragma unroll
        for (int k = 0; k < K_; k++) {
            float gum = -logf(-logf(u[k] + 1e-10f) + 1e-10f);
            float v = tp[t * K_ + k] + gum;
            if (v > best) { best = v; bi = k; }
        }
        sc[t] = (unsigned char)bi;
        g_ci[b * L_ + t] = (unsigned char)bi;
    } else if (t >= 64 && t < 128) {
        int e = t - 64;
        float s1 = 1.0f / (1.0f + expf(-th[e]));
        float s2 = 1.0f / (1.0f + expf(-ga[e]));
        sep[e] = s1 * s2;
    }
    if (t == 0) out[b] = 0.0f;
    __syncthreads();
    int g = t >> 5, l = t & 31;
    int cl = sc[l];
    unsigned bits = 0;
#pragma unroll
    for (int cj = 0; cj < K_; cj++) {
        float u = u_adj[((b * G_ + g) * K_ + cj) * K_ + cl];
        bits |= (u < sep[cj * K_ + cl]) ? (1u << cj) : 0u;
    }
    unsigned wv = 0;
#pragma unroll
    for (int j = 0; j < L_; j++) {
        unsigned mj = (bits >> sc[j]) & 1u;
        if (j == l) mj = 0;
        wv |= mj << j;
    }
    g_mask[(b * G_ + g) * L_ + l] = wv;
}

// ---------- smem layout (bytes) ----------
#define OFF_W1   0
#define OFF_W2   40960
#define OFF_SZS  81920
#define OFF_SZSH 86016
#define OFF_B1   90112
#define OFF_G1W  90624
#define OFF_G1B  91136
#define OFF_B2   91648
#define OFF_G2W  92160
#define OFF_G2B  92672
#define OFF_W3   93184
#define SMEM_BYTES 95232

__global__ __launch_bounds__(256, 1) void main_kernel(
    const float* __restrict__ z_sample, const int* __restrict__ target,
    const float* __restrict__ z_mean,   const float* __restrict__ z_logstd,
    const float* __restrict__ z_shared,
    const float* __restrict__ W1, const float* __restrict__ b1g,
    const float* __restrict__ g1wg, const float* __restrict__ g1bg,
    const float* __restrict__ W2, const float* __restrict__ b2g,
    const float* __restrict__ g2wg, const float* __restrict__ g2bg,
    const float* __restrict__ W3g, const float* __restrict__ b3g,
    const float* __restrict__ tsc, float* __restrict__ out)
{
    extern __shared__ char smem[];
    uint2*  W1u2 = (uint2*)(smem + OFF_W1);
    uint2*  W2u2 = (uint2*)(smem + OFF_W2);
    const uint4* W1q4 = (const uint4*)(smem + OFF_W1);
    const uint4* W2q4 = (const uint4*)(smem + OFF_W2);
    float*  szs  = (float*)(smem + OFF_SZS);
    float*  szsh = (float*)(smem + OFF_SZSH);
    float2* sB1  = (float2*)(smem + OFF_B1);
    float2* sG1w = (float2*)(smem + OFF_G1W);
    float2* sG1b = (float2*)(smem + OFF_G1B);
    float2* sB2  = (float2*)(smem + OFF_B2);
    float2* sG2w = (float2*)(smem + OFF_G2W);
    float2* sG2b = (float2*)(smem + OFF_G2B);
    float4* sW3  = (float4*)(smem + OFF_W3);

    const int tid = threadIdx.x;
    const int wid = tid >> 5;
    const int lane = tid & 31;
    const int gid = lane >> 2;
    const int t4 = lane & 3;

    const int start = (int)(((long long)blockIdx.x * NITEMS) / GRID_MAIN);
    const int end   = (int)(((long long)(blockIdx.x + 1) * NITEMS) / GRID_MAIN);

    int cur_l = -1;
    float b3_0 = 0.f, b3_1 = 0.f, sc0 = 1.f, sc1 = 1.f, isc0 = 1.f, isc1 = 1.f;

    for (int item = start; item < end; item++) {
        const int l = item >> 5;
        const int tile = item & 31;

        if (l != cur_l) {
            __syncthreads();
            const float* W1g = W1 + l * C_ * 104;
            for (int idx = tid; idx < 128 * 32; idx += 256) {
                int c = idx >> 5, s = idx & 31;
                int kk = s >> 2, tq = s & 3;
                int d0 = kk * 16 + tq * 2, d1 = d0 + 8;
                float w00 = (d0     < 104) ? W1g[c * 104 + d0]     : 0.0f;
                float w01 = (d0 + 1 < 104) ? W1g[c * 104 + d0 + 1] : 0.0f;
                float w10 = (d1     < 104) ? W1g[c * 104 + d1]     : 0.0f;
                float w11 = (d1 + 1 < 104) ? W1g[c * 104 + d1 + 1] : 0.0f;
                W1u2[c * 40 + (kk >> 1) * 8 + tq * 2 + (kk & 1)] =
                    make_uint2(pack2h(w00, w01), pack2h(w10, w11));
            }
            const float* W2g = W2 + l * C_ * C_;
            for (int idx = tid; idx < 128 * 32; idx += 256) {
                int c = idx >> 5, s = idx & 31;
                int kk = s >> 2, tq = s & 3;
                int d0 = kk * 16 + tq * 2, d1 = d0 + 8;
                W2u2[c * 40 + (kk >> 1) * 8 + tq * 2 + (kk & 1)] =
                    make_uint2(pack2h(W2g[c * C_ + d0], W2g[c * C_ + d0 + 1]),
                               pack2h(W2g[c * C_ + d1], W2g[c * C_ + d1 + 1]));
            }
            if (tid < 64) {
                sB1[tid]  = ((const float2*)(b1g  + l * C_))[tid];
                sG1w[tid] = ((const float2*)(g1wg + l * C_))[tid];
                sG1b[tid] = ((const float2*)(g1bg + l * C_))[tid];
                sB2[tid]  = ((const float2*)(b2g  + l * C_))[tid];
                sG2w[tid] = ((const float2*)(g2wg + l * C_))[tid];
                sG2b[tid] = ((const float2*)(g2bg + l * C_))[tid];
                int c0 = 2 * tid;
                sW3[tid] = make_float4(W3g[l * 2 * C_ + c0], W3g[l * 2 * C_ + C_ + c0],
                                       W3g[l * 2 * C_ + c0 + 1], W3g[l * 2 * C_ + C_ + c0 + 1]);
            }
            b3_0 = b3g[l * 2]; b3_1 = b3g[l * 2 + 1];
            sc0 = __expf(tsc[l * 2]); sc1 = __expf(tsc[l * 2 + 1]);
            isc0 = 1.0f / sc0; isc1 = 1.0f / sc1;
            __syncthreads();
            cur_l = l;
        }

        // stage z rows for this tile (32 b's)
        __syncthreads();
        for (int idx = tid; idx < 1024; idx += 256) {
            szs[idx]  = z_sample[tile * 32 * L_ + idx];
            szsh[idx] = z_shared[tile * 32 * S_ + idx];
        }
        __syncthreads();

        // warp owns 32 rows: 4 groups of 8; thread rows = gid + {0,8,16,24}
        unsigned Mw[4];
        bool tf[4];
        int tg[4];
#pragma unroll
        for (int k = 0; k < 4; k++) {
            int grow = tile * 256 + wid * 32 + k * 8 + gid;
            int bb = tile * 32 + wid * 4 + k;
            Mw[k] = g_mask[grow * L_ + l];
            tg[k] = target[bb];
            tf[k] = (g_ci[bb * L_ + l] == tg[k]);
        }

        // ---- build A1 fragments ----
        unsigned Ah0[7][4], Ah1[7][4];
        {
            const float* zr0 = szs  + (wid * 4 + 0) * 32;
            const float* zr1 = szs  + (wid * 4 + 1) * 32;
            const float* zr2 = szs  + (wid * 4 + 2) * 32;
            const float* zr3 = szs  + (wid * 4 + 3) * 32;
            const float* zh0 = szsh + (wid * 4 + 0) * 32;
            const float* zh1 = szsh + (wid * 4 + 1) * 32;
            const float* zh2 = szsh + (wid * 4 + 2) * 32;
            const float* zh3 = szsh + (wid * 4 + 3) * 32;
#pragma unroll
            for (int kk = 0; kk < 7; kk++) {
                int db = kk * 16 + t4 * 2;
                Ah0[kk][0] = pack2h(xval(db,     Mw[0], tf[0], tg[0], zr0, zh0),
                                    xval(db + 1, Mw[0], tf[0], tg[0], zr0, zh0));
                Ah0[kk][1] = pack2h(xval(db,     Mw[1], tf[1], tg[1], zr1, zh1),
                                    xval(db + 1, Mw[1], tf[1], tg[1], zr1, zh1));
                Ah0[kk][2] = pack2h(xval(db + 8, Mw[0], tf[0], tg[0], zr0, zh0),
                                    xval(db + 9, Mw[0], tf[0], tg[0], zr0, zh0));
                Ah0[kk][3] = pack2h(xval(db + 8, Mw[1], tf[1], tg[1], zr1, zh1),
                                    xval(db + 9, Mw[1], tf[1], tg[1], zr1, zh1));
                Ah1[kk][0] = pack2h(xval(db,     Mw[2], tf[2], tg[2], zr2, zh2),
                                    xval(db + 1, Mw[2], tf[2], tg[2], zr2, zh2));
                Ah1[kk][1] = pack2h(xval(db,     Mw[3], tf[3], tg[3], zr3, zh3),
                                    xval(db + 1, Mw[3], tf[3], tg[3], zr3, zh3));
                Ah1[kk][2] = pack2h(xval(db + 8, Mw[2], tf[2], tg[2], zr2, zh2),
                                    xval(db + 9, Mw[2], tf[2], tg[2], zr2, zh2));
                Ah1[kk][3] = pack2h(xval(db + 8, Mw[3], tf[3], tg[3], zr3, zh3),
                                    xval(db + 9, Mw[3], tf[3], tg[3], zr3, zh3));
            }
        }

        // ---- MMA1 (nt-outer, pack v to f16x2 immediately) ----
        unsigned vh0[16][2], vh1[16][2];
        float s[4] = {0.f, 0.f, 0.f, 0.f}, q[4] = {0.f, 0.f, 0.f, 0.f};
#pragma unroll
        for (int nt = 0; nt < 16; nt++) {
            float a0[4] = {0.f, 0.f, 0.f, 0.f}, a1[4] = {0.f, 0.f, 0.f, 0.f};
            const uint4* bp = W1q4 + (nt * 8 + gid) * 20 + t4;
#pragma unroll
            for (int j = 0; j < 4; j++) {
                uint4 bqv = bp[j * 4];
                mma_f16(a0, Ah0[2*j][0], Ah0[2*j][1], Ah0[2*j][2], Ah0[2*j][3], bqv.x, bqv.y);
                mma_f16(a1, Ah1[2*j][0], Ah1[2*j][1], Ah1[2*j][2], Ah1[2*j][3], bqv.x, bqv.y);
                if (j < 3) {
                    mma_f16(a0, Ah0[2*j+1][0], Ah0[2*j+1][1], Ah0[2*j+1][2], Ah0[2*j+1][3], bqv.z, bqv.w);
                    mma_f16(a1, Ah1[2*j+1][0], Ah1[2*j+1][1], Ah1[2*j+1][2], Ah1[2*j+1][3], bqv.z, bqv.w);
                }
            }
            float2 bb = sB1[nt * 4 + t4];
            a0[0] += bb.x; a0[1] += bb.y; a0[2] += bb.x; a0[3] += bb.y;
            a1[0] += bb.x; a1[1] += bb.y; a1[2] += bb.x; a1[3] += bb.y;
            s[0] += a0[0] + a0[1]; q[0] += a0[0]*a0[0] + a0[1]*a0[1];
            s[1] += a0[2] + a0[3]; q[1] += a0[2]*a0[2] + a0[3]*a0[3];
            s[2] += a1[0] + a1[1]; q[2] += a1[0]*a1[0] + a1[1]*a1[1];
            s[3] += a1[2] + a1[3]; q[3] += a1[2]*a1[2] + a1[3]*a1[3];
            vh0[nt][0] = pack2h(a0[0], a0[1]); vh0[nt][1] = pack2h(a0[2], a0[3]);
            vh1[nt][0] = pack2h(a1[0], a1[1]); vh1[nt][1] = pack2h(a1[2], a1[3]);
        }
#pragma unroll
        for (int o = 1; o <= 2; o <<= 1)
#pragma unroll
            for (int k = 0; k < 4; k++) {
                s[k] += __shfl_xor_sync(0xffffffffu, s[k], o);
                q[k] += __shfl_xor_sync(0xffffffffu, q[k], o);
            }
        float mu[4], inv[4];
#pragma unroll
        for (int k = 0; k < 4; k++) {
            mu[k] = s[k] * (1.0f / 128.0f);
            inv[k] = rsqrtf(q[k] * (1.0f / 128.0f) - mu[k] * mu[k] + 1e-5f);
        }

        // ---- GN1 + SiLU in place (vh becomes A2 fragments) ----
#pragma unroll
        for (int nt = 0; nt < 16; nt++) {
            float2 w = sG1w[nt * 4 + t4], bgn = sG1b[nt * 4 + t4];
            float2 f;
            f = unpack2h(vh0[nt][0]);
            vh0[nt][0] = pack2h(silu_f((f.x - mu[0]) * inv[0] * w.x + bgn.x),
                                silu_f((f.y - mu[0]) * inv[0] * w.y + bgn.y));
            f = unpack2h(vh0[nt][1]);
            vh0[nt][1] = pack2h(silu_f((f.x - mu[1]) * inv[1] * w.x + bgn.x),
                                silu_f((f.y - mu[1]) * inv[1] * w.y + bgn.y));
            f = unpack2h(vh1[nt][0]);
            vh1[nt][0] = pack2h(silu_f((f.x - mu[2]) * inv[2] * w.x + bgn.x),
                                silu_f((f.y - mu[2]) * inv[2] * w.y + bgn.y));
            f = unpack2h(vh1[nt][1]);
            vh1[nt][1] = pack2h(silu_f((f.x - mu[3]) * inv[3] * w.x + bgn.x),
                                silu_f((f.y - mu[3]) * inv[3] * w.y + bgn.y));
        }

        // ---- MMA2 (A2 = vh, nt-outer, pack outputs) ----
        unsigned vo0[16][2], vo1[16][2];
#pragma unroll
        for (int k = 0; k < 4; k++) { s[k] = 0.f; q[k] = 0.f; }
#pragma unroll
        for (int nt = 0; nt < 16; nt++) {
            float a0[4] = {0.f, 0.f, 0.f, 0.f}, a1[4] = {0.f, 0.f, 0.f, 0.f};
            const uint4* bp = W2q4 + (nt * 8 + gid) * 20 + t4;
#pragma unroll
            for (int j = 0; j < 4; j++) {
                uint4 bqv = bp[j * 4];
                mma_f16(a0, vh0[4*j][0],   vh0[4*j][1],   vh0[4*j+1][0], vh0[4*j+1][1], bqv.x, bqv.y);
                mma_f16(a1, vh1[4*j][0],   vh1[4*j][1],   vh1[4*j+1][0], vh1[4*j+1][1], bqv.x, bqv.y);
                mma_f16(a0, vh0[4*j+2][0], vh0[4*j+2][1], vh0[4*j+3][0], vh0[4*j+3][1], bqv.z, bqv.w);
                mma_f16(a1, vh1[4*j+2][0], vh1[4*j+2][1], vh1[4*j+3][0], vh1[4*j+3][1], bqv.z, bqv.w);
            }
            float2 bb = sB2[nt * 4 + t4];
            a0[0] += bb.x; a0[1] += bb.y; a0[2] += bb.x; a0[3] += bb.y;
            a1[0] += bb.x; a1[1] += bb.y; a1[2] += bb.x; a1[3] += bb.y;
            s[0] += a0[0] + a0[1]; q[0] += a0[0]*a0[0] + a0[1]*a0[1];
            s[1] += a0[2] + a0[3]; q[1] += a0[2]*a0[2] + a0[3]*a0[3];
            s[2] += a1[0] + a1[1]; q[2] += a1[0]*a1[0] + a1[1]*a1[1];
            s[3] += a1[2] + a1[3]; q[3] += a1[2]*a1[2] + a1[3]*a1[3];
            vo0[nt][0] = pack2h(a0[0], a0[1]); vo0[nt][1] = pack2h(a0[2], a0[3]);
            vo1[nt][0] = pack2h(a1[0], a1[1]); vo1[nt][1] = pack2h(a1[2], a1[3]);
        }
#pragma unroll
        for (int o = 1; o <= 2; o <<= 1)
#pragma unroll
            for (int k = 0; k < 4; k++) {
                s[k] += __shfl_xor_sync(0xffffffffu, s[k], o);
                q[k] += __shfl_xor_sync(0xffffffffu, q[k], o);
            }
#pragma unroll
        for (int k = 0; k < 4; k++) {
            mu[k] = s[k] * (1.0f / 128.0f);
            inv[k] = rsqrtf(q[k] * (1.0f / 128.0f) - mu[k] * mu[k] + 1e-5f);
        }

        // ---- GN2 + SiLU + layer3 + KL ----
        float p0[4] = {0.f, 0.f, 0.f, 0.f}, p1[4] = {0.f, 0.f, 0.f, 0.f};
#pragma unroll
        for (int nt = 0; nt < 16; nt++) {
            float2 wv = sG2w[nt * 4 + t4], bv = sG2b[nt * 4 + t4];
            float4 w3 = sW3[nt * 4 + t4];
            float2 f;
            f = unpack2h(vo0[nt][0]);
            {
                float h0 = silu_f((f.x - mu[0]) * inv[0] * wv.x + bv.x);
                float h1 = silu_f((f.y - mu[0]) * inv[0] * wv.y + bv.y);
                p0[0] += h0 * w3.x + h1 * w3.z;  p1[0] += h0 * w3.y + h1 * w3.w;
            }
            f = unpack2h(vo0[nt][1]);
            {
                float h0 = silu_f((f.x - mu[1]) * inv[1] * wv.x + bv.x);
                float h1 = silu_f((f.y - mu[1]) * inv[1] * wv.y + bv.y);
                p0[1] += h0 * w3.x + h1 * w3.z;  p1[1] += h0 * w3.y + h1 * w3.w;
            }
            f = unpack2h(vo1[nt][0]);
            {
                float h0 = silu_f((f.x - mu[2]) * inv[2] * wv.x + bv.x);
                float h1 = silu_f((f.y - mu[2]) * inv[2] * wv.y + bv.y);
                p0[2] += h0 * w3.x + h1 * w3.z;  p1[2] += h0 * w3.y + h1 * w3.w;
            }
            f = unpack2h(vo1[nt][1]);
            {
                float h0 = silu_f((f.x - mu[3]) * inv[3] * wv.x + bv.x);
                float h1 = silu_f((f.y - mu[3]) * inv[3] * wv.y + bv.y);
                p0[3] += h0 * w3.x + h1 * w3.z;  p1[3] += h0 * w3.y + h1 * w3.w;
            }
        }
#pragma unroll
        for (int o = 1; o <= 2; o <<= 1)
#pragma unroll
            for (int k = 0; k < 4; k++) {
                p0[k] += __shfl_xor_sync(0xffffffffu, p0[k], o);
                p1[k] += __shfl_xor_sync(0xffffffffu, p1[k], o);
            }
        if (t4 == 0) {
#pragma unroll
            for (int k = 0; k < 4; k++) {
                int bb = tile * 32 + wid * 4 + k;
                float o0 = p0[k] + b3_0, o1 = p1[k] + b3_1;
                float pm = tanhf(o0 * isc0) * sc0;
                float pl = tanhf(o1 * isc1) * sc1;
                float zl = z_logstd[bb * L_ + l], zmn = z_mean[bb * L_ + l];
                float dmu = zmn - pm;
                float kld = pl - zl + (__expf(2.0f * zl) + dmu * dmu) * 0.5f * __expf(-2.0f * pl) - 0.5f;
                atomicAdd(out + bb, kld * 0.125f);
            }
        }
    }
}

extern "C" void kernel_launch(void* const* d_in, const int* in_sizes, int n_in,
                              void* d_out, int out_size) {
    const float* z_sample      = (const float*)d_in[0];
    const int*   target        = (const int*)  d_in[1];
    const float* z_mean        = (const float*)d_in[2];
    const float* z_logstd      = (const float*)d_in[3];
    const float* z_shared      = (const float*)d_in[4];
    const float* u_gumbel      = (const float*)d_in[5];
    const float* u_adj         = (const float*)d_in[6];
    const float* target_params = (const float*)d_in[7];
    const float* enco_theta    = (const float*)d_in[8];
    const float* enco_gamma    = (const float*)d_in[9];
    const float* W1            = (const float*)d_in[10];
    const float* b1            = (const float*)d_in[11];
    const float* gn1_w         = (const float*)d_in[12];
    const float* gn1_b         = (const float*)d_in[13];
    const float* W2            = (const float*)d_in[14];
    const float* b2            = (const float*)d_in[15];
    const float* gn2_w         = (const float*)d_in[16];
    const float* gn2_b         = (const float*)d_in[17];
    const float* W3            = (const float*)d_in[18];
    const float* b3            = (const float*)d_in[19];
    const float* tanh_scale    = (const float*)d_in[20];
    float* out = (float*)d_out;

    prep_kernel<<<B_, 256>>>(target_params, u_gumbel, enco_theta, enco_gamma, u_adj, out);

    cudaFuncSetAttribute(main_kernel, cudaFuncAttributeMaxDynamicSharedMemorySize, SMEM_BYTES);
    main_kernel<<<GRID_MAIN, 256, SMEM_BYTES>>>(
        z_sample, target, z_mean, z_logstd, z_shared,
        W1, b1, gn1_w, gn1_b, W2, b2, gn2_w, gn2_b, W3, b3, tanh_scale, out);
}